// round 7
// baseline (speedup 1.0000x reference)
#include <cuda_runtime.h>
#include <stdint.h>

// ---------------------------------------------------------------------------
// DownsampleWithPruning — single fused persistent kernel, 3 phases with
// device-wide barriers (all 592 CTAs co-resident: 256 thr, <=64 regs, ~3KB smem).
//
// Phase A: ref+parent bitmap REDs, lookback-state reset, 80% of 260MB zero-fill
// Phase B: dual-value decoupled-lookback scan + emit (coords, rankBase, masked
//          list at deterministic positions), per-slice filter lists, 20% fill
// Phase C: coords pad, mask=1 + bias atomics, tap/half/slice conv scatter
// ---------------------------------------------------------------------------

#define WORDS   (1 << 20)      // 2^26 keys / 64
#define NCHUNK  1024           // lookback chunks
#define CWORDS  1024           // words per chunk
#define GRID    592
#define NTHR    256
#define GT      (GRID * NTHR)
#define NWARPS  (GT / 32)      // 4736
#define LCAP    64
#define MASK21  0x1FFFFFull

__device__ unsigned long long g_bitmap[WORDS];
__device__ unsigned long long g_refbit[WORDS];
__device__ unsigned long long g_state[NCHUNK];   // flag<<62 | rank<<21 | mask
__device__ int g_rankBase[WORDS];
__device__ int g_masked[1 << 20];
__device__ int g_M;
__device__ int g_mTotal;
__device__ int g_cntS[8][GRID];
__device__ int g_listS[8][GRID][LCAP];
__device__ int g_ovfl[8192];
__device__ int g_ovflCnt;
// epoch barrier state (never reset; replay-safe)
__device__ unsigned long long g_barSub[32];
__device__ unsigned long long g_barRoot;
__device__ unsigned long long g_barFlag;

__device__ __forceinline__ void gbarrier(int tid, int b) {
    __syncthreads();
    if (tid == 0) {
        volatile unsigned long long* flag = &g_barFlag;
        unsigned long long pre = *flag;          // before my arrival => safe
        __threadfence();
        int s = b & 31;
        unsigned long long cnt = 18ull + (s < 16 ? 1ull : 0ull);  // 592 total
        unsigned long long old = atomicAdd(&g_barSub[s], 1ull);
        if ((old + 1ull) % cnt == 0ull) {
            __threadfence();
            unsigned long long r = atomicAdd(&g_barRoot, 1ull);
            if ((r + 1ull) % 32ull == 0ull) {
                __threadfence();
                atomicAdd(&g_barFlag, 1ull);
            }
        }
        while (*flag == pre) __nanosleep(64);
    }
    __syncthreads();
    __threadfence();
}

__global__ void __launch_bounds__(NTHR, 4)
k_fused(const float* __restrict__ feats,
        const float* __restrict__ W,
        const float* __restrict__ bias,
        const int*   __restrict__ coords,
        const int*   __restrict__ ref,
        float* __restrict__ out,
        int N, int NR,
        long long featBase, long long maskBase, long long zeroLen) {
    __shared__ unsigned long long sh[NTHR];
    __shared__ int s_cnt[8];
    __shared__ int s_exR, s_exM;

    const int tid  = threadIdx.x;
    const int b    = blockIdx.x;
    const int gtid = b * NTHR + tid;
    const int lane = tid & 31;
    const int wg   = gtid >> 5;

    // ================= PHASE A =================
    for (int i = gtid; i < NCHUNK; i += GT) g_state[i] = 0ull;
    if (gtid == 0) g_ovflCnt = 0;

    const int4* rc4 = (const int4*)ref;
    for (int i = gtid; i < NR; i += GT) {
        int4 c = rc4[i];
        int key = (c.x << 24) | (c.y << 16) | (c.z << 8) | c.w;
        atomicOr(&g_refbit[key >> 6], 1ull << (key & 63));
    }
    const int4* c4 = (const int4*)coords;
    for (int i = gtid; i < N; i += GT) {
        int4 c = c4[i];
        int pkey = ((c.x << 24) | (c.y << 16) | (c.z << 8) | c.w) & ~0x00010101;
        atomicOr(&g_bitmap[pkey >> 6], 1ull << (pkey & 63));
    }
    // fill part A (80%)
    {
        long long n4 = zeroLen >> 2;
        long long splitA = (n4 * 4) / 5;
        float4* pf = (float4*)(out + featBase);
        float4 z = make_float4(0.f, 0.f, 0.f, 0.f);
        for (long long i = gtid; i < splitA; i += GT) __stcs(&pf[i], z);
    }
    gbarrier(tid, b);

    // ================= PHASE B =================
    // scan + emit chunks (decoupled lookback, dual value rank|mask)
    for (int c = b; c < NCHUNK; c += GRID) {
        int base = c * CWORDS + tid * 4;
        unsigned long long w[4], mw[4];
        int s = 0, m = 0;
#pragma unroll
        for (int j = 0; j < 4; j++) {
            w[j]  = __ldcg(&g_bitmap[base + j]);
            mw[j] = w[j] & __ldcg(&g_refbit[base + j]);
            s += __popcll(w[j]);
            m += __popcll(mw[j]);
        }
        unsigned long long tv = ((unsigned long long)s << 32) | (unsigned)m;
        sh[tid] = tv;
        __syncthreads();
        for (int off = 1; off < NTHR; off <<= 1) {
            unsigned long long t = (tid >= off) ? sh[tid - off] : 0ull;
            __syncthreads();
            sh[tid] += t;
            __syncthreads();
        }
        int thrExR = (int)(sh[tid] >> 32) - s;
        int thrExM = (int)(sh[tid] & 0xFFFFFFFFull) - m;
        int aggR = (int)(sh[NTHR - 1] >> 32);
        int aggM = (int)(sh[NTHR - 1] & 0xFFFFFFFFull);
        __syncthreads();

        if (tid == 0) {
            long long exR = 0, exM = 0;
            if (c == 0) {
                atomicExch(&g_state[0],
                           (2ull << 62) | ((unsigned long long)aggR << 21) |
                           (unsigned long long)aggM);
            } else {
                atomicExch(&g_state[c],
                           (1ull << 62) | ((unsigned long long)aggR << 21) |
                           (unsigned long long)aggM);
                int j = c - 1;
                while (true) {
                    unsigned long long v =
                        *((volatile unsigned long long*)&g_state[j]);
                    unsigned f = (unsigned)(v >> 62);
                    if (f == 0) continue;
                    exR += (long long)((v >> 21) & MASK21);
                    exM += (long long)(v & MASK21);
                    if (f == 2) break;
                    j--;
                }
                atomicExch(&g_state[c],
                           (2ull << 62) |
                           ((unsigned long long)(exR + aggR) << 21) |
                           (unsigned long long)(exM + aggM));
            }
            s_exR = (int)exR;
            s_exM = (int)exM;
            if (c == NCHUNK - 1) {
                g_M = (int)exR + aggR;
                g_mTotal = (int)exM + aggM;
            }
        }
        __syncthreads();

        int rank  = s_exR + thrExR;
        int mrank = s_exM + thrExM;
#pragma unroll
        for (int j = 0; j < 4; j++) {
            g_rankBase[base + j] = rank;
            unsigned long long ww = w[j];
            unsigned long long mm = mw[j];
            int keyhi = (base + j) << 6;
            while (ww) {
                int bpos = __ffsll((long long)ww) - 1;
                ww &= ww - 1;
                int k = keyhi | bpos;
                ((float4*)out)[rank] = make_float4((float)(k >> 24),
                                                   (float)((k >> 16) & 255),
                                                   (float)((k >> 8) & 255),
                                                   (float)(k & 255));
                if ((mm >> bpos) & 1ull) g_masked[mrank++] = rank;
                rank++;
            }
        }
        __syncthreads();
    }

    // filter: per-block item range, per-slice lists
    {
        if (tid < 8) s_cnt[tid] = 0;
        __syncthreads();
        int chunkN = (N + GRID - 1) / GRID;
        int i0 = b * chunkN;
        int i1 = i0 + chunkN; if (i1 > N) i1 = N;
        for (int i = i0 + tid; i < i1; i += NTHR) {
            int4 c = c4[i];
            int key  = (c.x << 24) | (c.y << 16) | (c.z << 8) | c.w;
            int pkey = key & ~0x00010101;
            if ((__ldcg(&g_refbit[pkey >> 6]) >> (pkey & 63)) & 1ull) {
                int tap = ((key >> 14) & 4) | ((key >> 7) & 2) | (key & 1);
                int lp = atomicAdd(&s_cnt[tap], 1);
                if (lp < LCAP) g_listS[tap][b][lp] = i;
                else {
                    int op = atomicAdd(&g_ovflCnt, 1);
                    if (op < 8192) g_ovfl[op] = (tap << 28) | i;
                }
            }
        }
        __syncthreads();
        if (tid < 8) g_cntS[tid][b] = s_cnt[tid] < LCAP ? s_cnt[tid] : LCAP;
    }

    // fill part B (20%) + tail
    {
        long long n4 = zeroLen >> 2;
        long long splitA = (n4 * 4) / 5;
        float4* pf = (float4*)(out + featBase);
        float4 z = make_float4(0.f, 0.f, 0.f, 0.f);
        for (long long i = splitA + gtid; i < n4; i += GT) __stcs(&pf[i], z);
        long long tail = zeroLen & 3;
        if (gtid < tail) out[featBase + (n4 << 2) + gtid] = 0.f;
    }
    gbarrier(tid, b);

    // ================= PHASE C =================
    int M = __ldcg(&g_M);
    {   // pad coords [M, N)
        float4 neg1 = make_float4(-1.f, -1.f, -1.f, -1.f);
        for (int r = M + gtid; r < N; r += GT) ((float4*)out)[r] = neg1;
    }
    {   // mask=1 + bias atomics
        float bv0 = __ldg(&bias[lane]);
        float bv1 = __ldg(&bias[32 + lane]);
        int mc = __ldcg(&g_mTotal);
        for (int i = wg; i < mc; i += NWARPS) {
            int r = __ldcg(&g_masked[i]);
            if (lane == 0) out[maskBase + r] = 1.0f;
            float* dst = out + featBase + (long long)r * 64;
            atomicAdd(dst + lane, bv0);
            atomicAdd(dst + 32 + lane, bv1);
        }
    }
    // conv: job = (tap, half, slice); each warp does 2 jobs
    for (int job = wg; job < 8 * 2 * GRID; job += NWARPS) {
        int tap   = job & 7;
        int half  = (job >> 3) & 1;
        int slice = job >> 4;
        int cnt = __ldcg(&g_cntS[tap][slice]);
        if (cnt == 0) continue;
        float wreg[32];
        const float* Wt = W + tap * 2048 + half * 32 + lane;
#pragma unroll
        for (int j = 0; j < 32; j++) wreg[j] = __ldg(&Wt[j * 64]);
        for (int k = 0; k < cnt; k++) {
            int n = __ldcg(&g_listS[tap][slice][k]);
            int4 c = c4[n];
            int pkey = ((c.x << 24) | (c.y << 16) | (c.z << 8) | c.w) & ~0x00010101;
            int word = pkey >> 6, bit = pkey & 63;
            int rank = __ldcg(&g_rankBase[word]) +
                       __popcll(__ldcg(&g_bitmap[word]) & ((1ull << bit) - 1ull));
            float f = __ldg(&feats[(long long)n * 32 + lane]);
            float a = 0.f;
#pragma unroll
            for (int j = 0; j < 32; j++)
                a += __shfl_sync(0xffffffffu, f, j) * wreg[j];
            atomicAdd(out + featBase + (long long)rank * 64 + half * 32 + lane, a);
        }
    }
    // overflow items (expected none)
    int oc = __ldcg(&g_ovflCnt);
    for (int e = wg; e < oc && e < 8192; e += NWARPS) {
        int v = __ldcg(&g_ovfl[e]);
        int tap = v >> 28, n = v & 0x0FFFFFFF;
        int4 c = c4[n];
        int pkey = ((c.x << 24) | (c.y << 16) | (c.z << 8) | c.w) & ~0x00010101;
        int word = pkey >> 6, bit = pkey & 63;
        int rank = __ldcg(&g_rankBase[word]) +
                   __popcll(__ldcg(&g_bitmap[word]) & ((1ull << bit) - 1ull));
        float f = __ldg(&feats[(long long)n * 32 + lane]);
        for (int half = 0; half < 2; half++) {
            float a = 0.f;
            for (int j = 0; j < 32; j++)
                a += __shfl_sync(0xffffffffu, f, j) *
                     __ldg(&W[tap * 2048 + j * 64 + half * 32 + lane]);
            atomicAdd(out + featBase + (long long)rank * 64 + half * 32 + lane, a);
        }
    }
}

extern "C" void kernel_launch(void* const* d_in, const int* in_sizes, int n_in,
                              void* d_out, int out_size) {
    const float* feats  = (const float*)d_in[0];
    const float* W      = (const float*)d_in[1];
    const float* bias   = (const float*)d_in[2];
    const int*   coords = (const int*)d_in[3];
    const int*   ref    = (const int*)d_in[4];
    float* out = (float*)d_out;

    int N  = in_sizes[3] / 4;
    int NR = in_sizes[4] / 4;
    long long featBase = 4LL * N;
    long long maskBase = (long long)out_size - N;          // == 68N
    long long zeroLen  = (long long)out_size - featBase;   // feats + mask (65N)

    k_fused<<<GRID, NTHR>>>(feats, W, bias, coords, ref, out,
                            N, NR, featBase, maskBase, zeroLen);
}

// round 8
// speedup vs baseline: 1.1646x; 1.1646x over previous
#include <cuda_runtime.h>
#include <stdint.h>

// ---------------------------------------------------------------------------
// DownsampleWithPruning — sparse stride-2 conv (2x2x2) + prune by ref set.
// Keyspace: b<<24 | x<<16 | y<<8 | z  in [0, 2^26)
//
// DAG:
//   s0: k_fill (260MB zeros, 592 blocks = half of each SM -> chain co-resides)
//   sB: k_setup (resets + ref/parent bitmaps) -> k_scanemit (dual lookback:
//       coords + rankBase + masked list, no contended atomics)
//   sC: [after setup] k_filter (per-(tap,block) slots, smem counters only)
//   s0: [after fill+emit+filter] k_biasconv (pad + mask/bias + conv scatter)
// ---------------------------------------------------------------------------

#define WORDS   (1 << 20)       // 2^26 keys / 64
#define NCHUNK  1024            // scan chunks
#define CWORDS  1024            // bitmap words per chunk
#define MASK21  0x1FFFFFull
#define FCH     1024            // filter items per block
#define FBLKMAX 1024
#define LCAP    64

__device__ unsigned long long g_bitmap[WORDS];   // parent-key occupancy (8MB)
__device__ unsigned long long g_refbit[WORDS];   // ref-key occupancy (8MB)
__device__ unsigned long long g_state[NCHUNK];   // flag<<62 | rank<<21 | mask
__device__ int g_rankBase[WORDS];
__device__ int g_masked[1 << 20];                // ranks of masked outputs
__device__ int g_M;                              // unique outputs
__device__ int g_mTotal;                         // masked outputs
__device__ int g_cntS[8][FBLKMAX];               // per-(tap,block) counts
__device__ int g_listS[8][FBLKMAX][LCAP];        // per-(tap,block) input idx
__device__ int g_ovfl[8192];
__device__ int g_ovflCnt;

// ---- streaming zero fill (592 blocks: co-residency with the side chain) ----
__global__ void __launch_bounds__(256) k_fill(float* __restrict__ out,
                                              long long startFloat,
                                              long long numFloats) {
    long long n4 = numFloats >> 2;
    float4* p = (float4*)(out + startFloat);
    float4 z = make_float4(0.f, 0.f, 0.f, 0.f);
    long long T = (long long)gridDim.x * blockDim.x;
    long long i = (long long)blockIdx.x * blockDim.x + threadIdx.x;
    for (; i + T < n4; i += 2 * T) {          // 2 independent stores in flight
        __stcs(&p[i], z);
        __stcs(&p[i + T], z);
    }
    if (i < n4) __stcs(&p[i], z);
    long long tail = numFloats & 3;
    if (blockIdx.x == 0 && threadIdx.x < tail)
        out[startFloat + (n4 << 2) + threadIdx.x] = 0.f;
}

// ---- setup: state resets + ref bitmap + parent bitmap ------------------------
__global__ void __launch_bounds__(256) k_setup(const int* __restrict__ coords, int N,
                                               const int* __restrict__ rc, int NR) {
    int tid = blockIdx.x * blockDim.x + threadIdx.x;
    int T = gridDim.x * blockDim.x;
    for (int i = tid; i < NCHUNK; i += T) g_state[i] = 0ull;
    if (tid == 0) g_ovflCnt = 0;

    const int4* rc4 = (const int4*)rc;
#pragma unroll 4
    for (int i = tid; i < NR; i += T) {
        int4 c = rc4[i];
        int key = (c.x << 24) | (c.y << 16) | (c.z << 8) | c.w;
        atomicOr(&g_refbit[key >> 6], 1ull << (key & 63));
    }
    const int4* c4 = (const int4*)coords;
#pragma unroll 4
    for (int i = tid; i < N; i += T) {
        int4 c = c4[i];
        int pkey = ((c.x << 24) | (c.y << 16) | (c.z << 8) | c.w) & ~0x00010101;
        atomicOr(&g_bitmap[pkey >> 6], 1ull << (pkey & 63));
    }
}

// ---- single-pass dual-value lookback scan + emit -----------------------------
__global__ void __launch_bounds__(256) k_scanemit(float* __restrict__ out) {
    __shared__ unsigned long long sh[256];
    __shared__ int s_exR, s_exM;
    int tid = threadIdx.x, c = blockIdx.x;

    int base = c * CWORDS + tid * 4;
    unsigned long long w[4], mw[4];
    int s = 0, m = 0;
#pragma unroll
    for (int j = 0; j < 4; j++) {
        w[j]  = g_bitmap[base + j];
        mw[j] = w[j] & g_refbit[base + j];
        s += __popcll(w[j]);
        m += __popcll(mw[j]);
    }
    sh[tid] = ((unsigned long long)s << 32) | (unsigned)m;
    __syncthreads();
    for (int off = 1; off < 256; off <<= 1) {
        unsigned long long t = (tid >= off) ? sh[tid - off] : 0ull;
        __syncthreads();
        sh[tid] += t;
        __syncthreads();
    }
    int thrExR = (int)(sh[tid] >> 32) - s;
    int thrExM = (int)(sh[tid] & 0xFFFFFFFFull) - m;
    int aggR = (int)(sh[255] >> 32);
    int aggM = (int)(sh[255] & 0xFFFFFFFFull);

    if (tid == 0) {
        long long exR = 0, exM = 0;
        if (c == 0) {
            atomicExch(&g_state[0], (2ull << 62) |
                       ((unsigned long long)aggR << 21) | (unsigned long long)aggM);
        } else {
            atomicExch(&g_state[c], (1ull << 62) |
                       ((unsigned long long)aggR << 21) | (unsigned long long)aggM);
            int j = c - 1;
            while (true) {
                unsigned long long v = *((volatile unsigned long long*)&g_state[j]);
                unsigned f = (unsigned)(v >> 62);
                if (f == 0) continue;
                exR += (long long)((v >> 21) & MASK21);
                exM += (long long)(v & MASK21);
                if (f == 2) break;
                j--;
            }
            atomicExch(&g_state[c], (2ull << 62) |
                       ((unsigned long long)(exR + aggR) << 21) |
                       (unsigned long long)(exM + aggM));
        }
        s_exR = (int)exR;
        s_exM = (int)exM;
        if (c == NCHUNK - 1) { g_M = (int)exR + aggR; g_mTotal = (int)exM + aggM; }
    }
    __syncthreads();

    int rank  = s_exR + thrExR;
    int mrank = s_exM + thrExM;
#pragma unroll
    for (int j = 0; j < 4; j++) {
        g_rankBase[base + j] = rank;
        unsigned long long ww = w[j];
        unsigned long long mm = mw[j];
        int keyhi = (base + j) << 6;
        while (ww) {
            int bpos = __ffsll((long long)ww) - 1;
            ww &= ww - 1;
            int k = keyhi | bpos;
            ((float4*)out)[rank] = make_float4((float)(k >> 24),
                                               (float)((k >> 16) & 255),
                                               (float)((k >> 8) & 255),
                                               (float)(k & 255));
            if ((mm >> bpos) & 1ull) g_masked[mrank++] = rank;
            rank++;
        }
    }
}

// ---- filter: per-(tap,block) slots, smem counters only -----------------------
__global__ void __launch_bounds__(256) k_filter(const int* __restrict__ coords, int N) {
    __shared__ int s_cnt[8];
    int tid = threadIdx.x, b = blockIdx.x;
    if (tid < 8) s_cnt[tid] = 0;
    __syncthreads();
    int base = b * FCH;
    const int4* c4 = (const int4*)coords;
#pragma unroll
    for (int r = 0; r < FCH / 256; r++) {
        int i = base + r * 256 + tid;
        if (i < N) {
            int4 c = c4[i];
            int key  = (c.x << 24) | (c.y << 16) | (c.z << 8) | c.w;
            int pkey = key & ~0x00010101;
            if ((g_refbit[pkey >> 6] >> (pkey & 63)) & 1ull) {
                int tap = ((key >> 14) & 4) | ((key >> 7) & 2) | (key & 1);
                int lp = atomicAdd(&s_cnt[tap], 1);
                if (lp < LCAP) g_listS[tap][b][lp] = i;
                else {
                    int op = atomicAdd(&g_ovflCnt, 1);
                    if (op < 8192) g_ovfl[op] = (tap << 28) | i;
                }
            }
        }
    }
    __syncthreads();
    if (tid < 8) g_cntS[tid][b] = s_cnt[tid] < LCAP ? s_cnt[tid] : LCAP;
}

// ---- pad coords + mask=1 + bias + conv scatter -------------------------------
__global__ void __launch_bounds__(256) k_biasconv(const float* __restrict__ feats,
                                                  const float* __restrict__ W,
                                                  const int* __restrict__ coords,
                                                  const float* __restrict__ bias,
                                                  float* __restrict__ out,
                                                  int N, int FBLK,
                                                  long long featBase,
                                                  long long maskBase) {
    int lane = threadIdx.x & 31;
    int gtid = blockIdx.x * blockDim.x + threadIdx.x;
    int Tthr = gridDim.x * blockDim.x;
    int gw   = gtid >> 5;
    int totalWarps = Tthr >> 5;
    const int4* c4 = (const int4*)coords;

    // pad coords rows [g_M, N)
    int M = g_M;
    float4 neg1 = make_float4(-1.f, -1.f, -1.f, -1.f);
    for (int r = M + gtid; r < N; r += Tthr) ((float4*)out)[r] = neg1;

    // mask=1 + bias atomics
    float bv0 = __ldg(&bias[lane]);
    float bv1 = __ldg(&bias[32 + lane]);
    int mc = g_mTotal;
    for (int i = gw; i < mc; i += totalWarps) {
        int r = g_masked[i];
        if (lane == 0) out[maskBase + r] = 1.0f;
        float* dst = out + featBase + (long long)r * 64;
        atomicAdd(dst + lane, bv0);
        atomicAdd(dst + 32 + lane, bv1);
    }

    // conv: job = (tap, half, slice)
    for (int job = gw; job < 16 * FBLK; job += totalWarps) {
        int tap   = job & 7;
        int half  = (job >> 3) & 1;
        int slice = job >> 4;
        int cnt = g_cntS[tap][slice];
        if (cnt == 0) continue;
        float wreg[32];
        const float* Wt = W + tap * 2048 + half * 32 + lane;
#pragma unroll
        for (int j = 0; j < 32; j++) wreg[j] = __ldg(&Wt[j * 64]);
        for (int k = 0; k < cnt; k++) {
            int n = g_listS[tap][slice][k];
            int4 c = c4[n];
            int pkey = ((c.x << 24) | (c.y << 16) | (c.z << 8) | c.w) & ~0x00010101;
            int word = pkey >> 6, bit = pkey & 63;
            int rank = g_rankBase[word] +
                       __popcll(g_bitmap[word] & ((1ull << bit) - 1ull));
            float f = __ldg(&feats[(long long)n * 32 + lane]);
            float a = 0.f;
#pragma unroll
            for (int j = 0; j < 32; j++)
                a += __shfl_sync(0xffffffffu, f, j) * wreg[j];
            atomicAdd(out + featBase + (long long)rank * 64 + half * 32 + lane, a);
        }
    }

    // overflow (expected empty)
    int oc = g_ovflCnt;
    for (int e = gw; e < oc && e < 8192; e += totalWarps) {
        int v = g_ovfl[e];
        int tap = v >> 28, n = v & 0x0FFFFFFF;
        int4 c = c4[n];
        int pkey = ((c.x << 24) | (c.y << 16) | (c.z << 8) | c.w) & ~0x00010101;
        int word = pkey >> 6, bit = pkey & 63;
        int rank = g_rankBase[word] +
                   __popcll(g_bitmap[word] & ((1ull << bit) - 1ull));
        float f = __ldg(&feats[(long long)n * 32 + lane]);
        for (int half = 0; half < 2; half++) {
            float a = 0.f;
            for (int j = 0; j < 32; j++)
                a += __shfl_sync(0xffffffffu, f, j) *
                     __ldg(&W[tap * 2048 + j * 64 + half * 32 + lane]);
            atomicAdd(out + featBase + (long long)rank * 64 + half * 32 + lane, a);
        }
    }
}

// ---- streams/events created at load time (no device-memory allocation) -----
static cudaStream_t g_sB, g_sC;
static cudaEvent_t  g_evFork, g_evSetup, g_evEmit, g_evFilter;
namespace {
struct ResInit {
    ResInit() {
        cudaStreamCreateWithFlags(&g_sB, cudaStreamNonBlocking);
        cudaStreamCreateWithFlags(&g_sC, cudaStreamNonBlocking);
        cudaEventCreateWithFlags(&g_evFork,   cudaEventDisableTiming);
        cudaEventCreateWithFlags(&g_evSetup,  cudaEventDisableTiming);
        cudaEventCreateWithFlags(&g_evEmit,   cudaEventDisableTiming);
        cudaEventCreateWithFlags(&g_evFilter, cudaEventDisableTiming);
    }
};
static ResInit g_resInit;
}

extern "C" void kernel_launch(void* const* d_in, const int* in_sizes, int n_in,
                              void* d_out, int out_size) {
    const float* feats  = (const float*)d_in[0];
    const float* W      = (const float*)d_in[1];
    const float* bias   = (const float*)d_in[2];
    const int*   coords = (const int*)d_in[3];
    const int*   ref    = (const int*)d_in[4];
    float* out = (float*)d_out;

    int N  = in_sizes[3] / 4;
    int NR = in_sizes[4] / 4;
    int FBLK = (N + FCH - 1) / FCH;
    long long featBase = 4LL * N;
    long long maskBase = (long long)out_size - N;          // == 68N
    long long zeroLen  = (long long)out_size - featBase;   // feats + mask (65N)

    cudaEventRecord(g_evFork, 0);
    cudaStreamWaitEvent(g_sB, g_evFork, 0);
    cudaStreamWaitEvent(g_sC, g_evFork, 0);

    // s0: big zero fill at half-SM occupancy (leaves room for the chain)
    k_fill<<<592, 256, 0, 0>>>(out, featBase, zeroLen);

    // sB: setup -> scanemit (co-resident with fill)
    k_setup<<<592, 256, 0, g_sB>>>(coords, N, ref, NR);
    cudaEventRecord(g_evSetup, g_sB);
    k_scanemit<<<NCHUNK, 256, 0, g_sB>>>(out);
    cudaEventRecord(g_evEmit, g_sB);

    // sC: filter (needs refbit)
    cudaStreamWaitEvent(g_sC, g_evSetup, 0);
    k_filter<<<FBLK, 256, 0, g_sC>>>(coords, N);
    cudaEventRecord(g_evFilter, g_sC);

    // s0: join -> biasconv
    cudaStreamWaitEvent(0, g_evEmit, 0);
    cudaStreamWaitEvent(0, g_evFilter, 0);
    k_biasconv<<<1184, 256, 0, 0>>>(feats, W, coords, bias, out,
                                    N, FBLK, featBase, maskBase);
}